// round 12
// baseline (speedup 1.0000x reference)
#include <cuda_runtime.h>

// ---------------------------------------------------------------------------
// Scratch (device globals — no dynamic allocation allowed)
// ---------------------------------------------------------------------------
__device__ float g_p0[8 * 64 * 2 * 64 * 64];   // pooled input   (n,t,2,64,64)  16 MB
__device__ float g_h1[8 * 64 * 4 * 64 * 64];   // conv1 out      (n,t,4,64,64)  33.5 MB
__device__ float g_p1[8 * 64 * 4 * 16 * 16];   // pooled spikes1 (n,t,4,16,16)   2 MB
__device__ float g_h2[8 * 64 * 8 * 16 * 16];   // conv2 out      (n,t,8,16,16)   4 MB
__device__ float g_p2[8 * 64 * 128];           // features       (n,t,128)     256 KB

// ---- f32x2 packed helpers --------------------------------------------------
__device__ __forceinline__ unsigned long long pack2(float a, float b) {
    unsigned long long r;
    asm("mov.b64 %0, {%1, %2};" : "=l"(r) : "r"(__float_as_uint(a)), "r"(__float_as_uint(b)));
    return r;
}
__device__ __forceinline__ unsigned long long fma2(unsigned long long a,
                                                   unsigned long long b,
                                                   unsigned long long c) {
    unsigned long long d;
    asm("fma.rn.f32x2 %0, %1, %2, %3;" : "=l"(d) : "l"(a), "l"(b), "l"(c));
    return d;
}
__device__ __forceinline__ float2 unpack2(unsigned long long v) {
    unsigned lo, hi;
    asm("mov.b64 {%0, %1}, %2;" : "=r"(lo), "=r"(hi) : "l"(v));
    return make_float2(__uint_as_float(lo), __uint_as_float(hi));
}

// ---------------------------------------------------------------------------
// K1: avgpool4 of inp (8,2,256,256,64) -> g_p0 (n,t,2,64,64). One output
// pixel per thread, 16 independent LDG.128 -> deep MLP; 4096 blocks for
// 8 resident blocks/SM (64 warps). Padded-smem transpose, coalesced-ish writes.
// ---------------------------------------------------------------------------
__global__ __launch_bounds__(256) void k_pool(const float* __restrict__ inp) {
    int bx = blockIdx.x;                     // 256 = Y(64) x Xq(4)
    int Y = bx >> 2, Xq = bx & 3;
    int c = blockIdx.y, n = blockIdx.z;
    __shared__ float sm[16 * 65];
    int tid = threadIdx.x;
    int t4 = tid & 15, Xi = tid >> 4;        // Xi 0..15
    int X = Xq * 16 + Xi;
    const float4* base =
        reinterpret_cast<const float4*>(inp + (((long long)(n * 2 + c) * 256 + 4 * Y) * 256) * 64) + t4;
    float4 acc = make_float4(0.f, 0.f, 0.f, 0.f);
#pragma unroll
    for (int dy = 0; dy < 4; ++dy)
#pragma unroll
        for (int dx = 0; dx < 4; ++dx) {
            float4 v = base[(dy * 256 + 4 * X + dx) * 16];
            acc.x += v.x; acc.y += v.y; acc.z += v.z; acc.w += v.w;
        }
    sm[Xi * 65 + 4 * t4 + 0] = acc.x * 0.0625f;
    sm[Xi * 65 + 4 * t4 + 1] = acc.y * 0.0625f;
    sm[Xi * 65 + 4 * t4 + 2] = acc.z * 0.0625f;
    sm[Xi * 65 + 4 * t4 + 3] = acc.w * 0.0625f;
    __syncthreads();
    float* ob = g_p0 + n * 524288 + c * 4096 + Y * 64 + Xq * 16;
#pragma unroll
    for (int k = 0; k < 4; ++k) {
        int idx = k * 256 + tid;
        int tw = idx >> 4, Xw = idx & 15;
        ob[tw * 8192 + Xw] = sm[Xw * 65 + tw];
    }
}

// ---------------------------------------------------------------------------
// K2: conv7 (2->4ch) on 64x64, 8-row tiles (R9 winner): thread = 2 y-rows
// x 4 couts x 2 t (f32x2). Grid (ytile8 8, tp 32, n 8) = 2048 blocks x 256.
// ---------------------------------------------------------------------------
__global__ __launch_bounds__(256) void k_conv1mm(const float* __restrict__ w0) {
    int tile = blockIdx.x, tp = blockIdx.y, n = blockIdx.z;
    int t0 = tp * 2;
    int tid = threadIdx.x;
    int x = tid & 63, q = tid >> 6;          // q: row-pair (rows 2q, 2q+1 of 8)

    __shared__ float2 si[1960];              // [cin 2][row 14][col 70], (t0,t1)
    __shared__ ulonglong2 swq[98][2];        // per tap: {(w0,w0),(w1,w1)},{(w2,w2),(w3,w3)}

    if (tid < 98) {
        int cin = tid / 49, j = tid - cin * 49;
        float wa = w0[(0 * 2 + cin) * 49 + j];
        float wb = w0[(1 * 2 + cin) * 49 + j];
        float wc = w0[(2 * 2 + cin) * 49 + j];
        float wd = w0[(3 * 2 + cin) * 49 + j];
        swq[tid][0] = make_ulonglong2(pack2(wa, wa), pack2(wb, wb));
        swq[tid][1] = make_ulonglong2(pack2(wc, wc), pack2(wd, wd));
    }

    int Y0 = tile * 8;
    const float* pt0 = g_p0 + n * 524288 + t0 * 8192;
    const float* pt1 = pt0 + 8192;
    for (int e = tid; e < 1960; e += 256) {
        int cin = e / 980, rem = e - cin * 980;
        int r = rem / 70, col = rem - r * 70;
        int gy = Y0 - 3 + r, gx = col - 3;
        float2 v = make_float2(0.f, 0.f);
        if ((unsigned)gy < 64u && (unsigned)gx < 64u) {
            int off = cin * 4096 + gy * 64 + gx;
            v.x = pt0[off];
            v.y = pt1[off];
        }
        si[e] = v;
    }
    __syncthreads();

    unsigned long long a[2][4];              // [row r][cout]
#pragma unroll
    for (int r = 0; r < 2; ++r)
#pragma unroll
        for (int co = 0; co < 4; ++co) a[r][co] = 0ull;

    const unsigned long long* sb = reinterpret_cast<const unsigned long long*>(si);
#pragma unroll 1
    for (int dx = 0; dx < 7; ++dx) {
#pragma unroll
        for (int cin = 0; cin < 2; ++cin) {
            const unsigned long long* colp = sb + cin * 980 + (q * 2) * 70 + (x + dx);
            unsigned long long v[8];
#pragma unroll
            for (int r = 0; r < 8; ++r) v[r] = colp[r * 70];
#pragma unroll
            for (int dy = 0; dy < 7; ++dy) {
                ulonglong2 wA = swq[cin * 49 + dy * 7 + dx][0];
                ulonglong2 wB = swq[cin * 49 + dy * 7 + dx][1];
                a[0][0] = fma2(v[dy],     wA.x, a[0][0]);
                a[0][1] = fma2(v[dy],     wA.y, a[0][1]);
                a[0][2] = fma2(v[dy],     wB.x, a[0][2]);
                a[0][3] = fma2(v[dy],     wB.y, a[0][3]);
                a[1][0] = fma2(v[dy + 1], wA.x, a[1][0]);
                a[1][1] = fma2(v[dy + 1], wA.y, a[1][1]);
                a[1][2] = fma2(v[dy + 1], wB.x, a[1][2]);
                a[1][3] = fma2(v[dy + 1], wB.y, a[1][3]);
            }
        }
    }

    long long base = ((long long)(n * 64 + t0) * 4) * 4096;
    int ybase = Y0 + q * 2;
#pragma unroll
    for (int r = 0; r < 2; ++r)
#pragma unroll
        for (int co = 0; co < 4; ++co) {
            float2 f = unpack2(a[r][co]);
            g_h1[base + co * 4096 + (ybase + r) * 64 + x]         = f.x;
            g_h1[base + 16384 + co * 4096 + (ybase + r) * 64 + x] = f.y;
        }
}

// ---------------------------------------------------------------------------
// K3: IAF scan layer 1 + fused avgpool4 -> g_p1. 2-deep prefetch.
// ---------------------------------------------------------------------------
__global__ __launch_bounds__(256) void k_iaf1() {
    int Yp = blockIdx.x, co = blockIdx.y, n = blockIdx.z;
    int tid = threadIdx.x;
    int w = tid >> 5, lane = tid & 31;
    int yin = lane >> 3, x8 = lane & 7;
    int x = w * 8 + x8;
    int y = Yp * 4 + yin;

    const float* hb = g_h1 + (long long)(n * 64) * 16384 + co * 4096 + y * 64 + x;
    float* ob = g_p1 + (n * 64) * 1024 + co * 256 + Yp * 16 + (x >> 2);
    const unsigned m = 0xffffffffu;

    float v = 0.f;
    float n0 = hb[0];
    float n1 = hb[16384];
    for (int t = 0; t < 64; ++t) {
        float hv = n0;
        n0 = n1;
        if (t < 62) n1 = hb[(t + 2) * 16384];
        v += hv;
        float sp = (v >= 1.f) ? 1.f : 0.f;
        v -= sp;
        sp += __shfl_down_sync(m, sp, 1);
        sp += __shfl_down_sync(m, sp, 2);
        sp += __shfl_down_sync(m, sp, 8);
        sp += __shfl_down_sync(m, sp, 16);
        if (yin == 0 && (x8 & 3) == 0) ob[t * 1024] = sp * 0.0625f;
    }
}

// ---------------------------------------------------------------------------
// K4: conv7 (4->8ch) on 16x16, t-pair packed, full cout fan-out:
// thread = 2 y-rows x 8 couts x 2 t = 16 f32x2 accums. Block 128 = one
// t-pair (16x x 8 ypairs). Grid (tp 32, n 8) = 256 blocks.
// Per (cin,dx): 8 LDS.64 data + 28 bcast weight LDS feed 112 FMA2.
// ---------------------------------------------------------------------------
__global__ __launch_bounds__(128) void k_conv2mm(const float* __restrict__ w1) {
    int tp = blockIdx.x, n = blockIdx.y;
    int t0 = tp * 2;
    int tid = threadIdx.x;
    int x = tid & 15, yp = tid >> 4;         // yp 0..7 -> rows 2yp, 2yp+1

    __shared__ float2 si[1936];              // [cin 4][22][22], (t0,t1)
    __shared__ ulonglong2 swq[196][4];       // per tap: 8 couts as 4 (w,w)-pair regs

    for (int e = tid; e < 196; e += 128) {
        int cin = e / 49, k = e - cin * 49;
#pragma unroll
        for (int p = 0; p < 4; ++p) {
            float wa = w1[((2 * p + 0) * 4 + cin) * 49 + k];
            float wb = w1[((2 * p + 1) * 4 + cin) * 49 + k];
            swq[e][p] = make_ulonglong2(pack2(wa, wa), pack2(wb, wb));
        }
    }

    const float* pt0 = g_p1 + n * 65536 + t0 * 1024;
    const float* pt1 = pt0 + 1024;
    for (int e = tid; e < 1936; e += 128) {
        int cin = e / 484, rem = e - cin * 484;
        int r = rem / 22, col = rem - r * 22;
        int gy = r - 3, gx = col - 3;
        float2 v = make_float2(0.f, 0.f);
        if ((unsigned)gy < 16u && (unsigned)gx < 16u) {
            int off = cin * 256 + gy * 16 + gx;
            v.x = pt0[off];
            v.y = pt1[off];
        }
        si[e] = v;
    }
    __syncthreads();

    unsigned long long a[2][8];              // [row r][cout]
#pragma unroll
    for (int r = 0; r < 2; ++r)
#pragma unroll
        for (int co = 0; co < 8; ++co) a[r][co] = 0ull;

    const unsigned long long* sb = reinterpret_cast<const unsigned long long*>(si);
#pragma unroll 1
    for (int dx = 0; dx < 7; ++dx) {
#pragma unroll
        for (int cin = 0; cin < 4; ++cin) {
            const unsigned long long* colp = sb + cin * 484 + (yp * 2) * 22 + (x + dx);
            unsigned long long v[8];
#pragma unroll
            for (int r = 0; r < 8; ++r) v[r] = colp[r * 22];
#pragma unroll
            for (int dy = 0; dy < 7; ++dy) {
                const ulonglong2* wq = swq[cin * 49 + dy * 7 + dx];
                ulonglong2 w01 = wq[0], w23 = wq[1], w45 = wq[2], w67 = wq[3];
                a[0][0] = fma2(v[dy], w01.x, a[0][0]);
                a[0][1] = fma2(v[dy], w01.y, a[0][1]);
                a[0][2] = fma2(v[dy], w23.x, a[0][2]);
                a[0][3] = fma2(v[dy], w23.y, a[0][3]);
                a[0][4] = fma2(v[dy], w45.x, a[0][4]);
                a[0][5] = fma2(v[dy], w45.y, a[0][5]);
                a[0][6] = fma2(v[dy], w67.x, a[0][6]);
                a[0][7] = fma2(v[dy], w67.y, a[0][7]);
                a[1][0] = fma2(v[dy + 1], w01.x, a[1][0]);
                a[1][1] = fma2(v[dy + 1], w01.y, a[1][1]);
                a[1][2] = fma2(v[dy + 1], w23.x, a[1][2]);
                a[1][3] = fma2(v[dy + 1], w23.y, a[1][3]);
                a[1][4] = fma2(v[dy + 1], w45.x, a[1][4]);
                a[1][5] = fma2(v[dy + 1], w45.y, a[1][5]);
                a[1][6] = fma2(v[dy + 1], w67.x, a[1][6]);
                a[1][7] = fma2(v[dy + 1], w67.y, a[1][7]);
            }
        }
    }

    float* hb = g_h2 + (long long)(n * 64 + t0) * 2048;
#pragma unroll
    for (int r = 0; r < 2; ++r) {
        int yo = (yp * 2 + r) * 16 + x;
#pragma unroll
        for (int co = 0; co < 8; ++co) {
            float2 f = unpack2(a[r][co]);
            hb[co * 256 + yo]        = f.x;   // t0
            hb[2048 + co * 256 + yo] = f.y;   // t0+1
        }
    }
}

// ---------------------------------------------------------------------------
// K5: IAF scan layer 2 + avgpool4 -> g_p2 (n,t,128). 2-deep prefetch.
// ---------------------------------------------------------------------------
__global__ __launch_bounds__(256) void k_iaf2() {
    int co = blockIdx.x, n = blockIdx.y;
    int tid = threadIdx.x;
    int w = tid >> 5, lane = tid & 31;
    int yin = lane >> 3, x8 = lane & 7;
    int y = (w >> 1) * 4 + yin;
    int x = (w & 1) * 8 + x8;
    int g = (y >> 2) * 4 + (x >> 2);

    const float* hb = g_h2 + (long long)(n * 64) * 2048 + co * 256 + y * 16 + x;
    float* ob = g_p2 + (n * 64) * 128 + co * 16 + g;
    const unsigned m = 0xffffffffu;

    float v = 0.f;
    float n0 = hb[0];
    float n1 = hb[2048];
    for (int t = 0; t < 64; ++t) {
        float hv = n0;
        n0 = n1;
        if (t < 62) n1 = hb[(t + 2) * 2048];
        v += hv;
        float sp = (v >= 1.f) ? 1.f : 0.f;
        v -= sp;
        sp += __shfl_down_sync(m, sp, 1);
        sp += __shfl_down_sync(m, sp, 2);
        sp += __shfl_down_sync(m, sp, 8);
        sp += __shfl_down_sync(m, sp, 16);
        if (yin == 0 && (x8 & 3) == 0) ob[t * 128] = sp * 0.0625f;
    }
}

// ---------------------------------------------------------------------------
// K6: out[n][cls][t] = sum_f feat[n][t][f] * wl[cls][f]   -> (8,2,64)
// ---------------------------------------------------------------------------
__global__ __launch_bounds__(128) void k_fc(const float* __restrict__ wl,
                                            float* __restrict__ out) {
    int b = blockIdx.x;          // n*64 + t
    int tid = threadIdx.x;
    float v = g_p2[b * 128 + tid];
    float c0 = v * wl[tid];
    float c1 = v * wl[128 + tid];
    const unsigned m = 0xffffffffu;
#pragma unroll
    for (int o = 16; o; o >>= 1) {
        c0 += __shfl_down_sync(m, c0, o);
        c1 += __shfl_down_sync(m, c1, o);
    }
    __shared__ float r0[4], r1[4];
    if ((tid & 31) == 0) { r0[tid >> 5] = c0; r1[tid >> 5] = c1; }
    __syncthreads();
    if (tid == 0) {
        int n = b >> 6, t = b & 63;
        out[n * 128 + t]      = (r0[0] + r0[1]) + (r0[2] + r0[3]);
        out[n * 128 + 64 + t] = (r1[0] + r1[1]) + (r1[2] + r1[3]);
    }
}

// ---------------------------------------------------------------------------
extern "C" void kernel_launch(void* const* d_in, const int* in_sizes, int n_in,
                              void* d_out, int out_size) {
    const float *inp = nullptr, *w0 = nullptr, *w1 = nullptr, *wl = nullptr;
    for (int i = 0; i < n_in; ++i) {
        switch (in_sizes[i]) {
            case 67108864: inp = (const float*)d_in[i]; break;  // (8,2,256,256,64)
            case 392:      w0  = (const float*)d_in[i]; break;  // (4,2,7,7)
            case 1568:     w1  = (const float*)d_in[i]; break;  // (8,4,7,7)
            case 256:      wl  = (const float*)d_in[i]; break;  // (2,128)
        }
    }
    if (!inp) inp = (const float*)d_in[0];
    if (!w0)  w0  = (const float*)d_in[1];
    if (!w1)  w1  = (const float*)d_in[2];
    if (!wl)  wl  = (const float*)d_in[3];

    k_pool   <<<dim3(256, 2, 8), 256>>>(inp);
    k_conv1mm<<<dim3(8, 32, 8),  256>>>(w0);
    k_iaf1   <<<dim3(16, 4, 8),  256>>>();
    k_conv2mm<<<dim3(32, 8),     128>>>(w1);
    k_iaf2   <<<dim3(8, 8),      256>>>();
    k_fc     <<<512,             128>>>(wl, (float*)d_out);
}

// round 14
// speedup vs baseline: 1.0048x; 1.0048x over previous
#include <cuda_runtime.h>

// ---------------------------------------------------------------------------
// Scratch (device globals — no dynamic allocation allowed)
// ---------------------------------------------------------------------------
__device__ float g_p0[8 * 64 * 2 * 64 * 64];   // pooled input   (n,t,2,64,64)  16 MB
__device__ float g_h1[8 * 64 * 4 * 64 * 64];   // conv1 out      (n,t,4,64,64)  33.5 MB
__device__ float g_p1[8 * 64 * 4 * 16 * 16];   // pooled spikes1 (n,t,4,16,16)   2 MB
__device__ float g_h2[8 * 64 * 8 * 16 * 16];   // conv2 out      (n,t,8,16,16)   4 MB
__device__ float g_p2[8 * 64 * 128];           // features       (n,t,128)     256 KB

// ---- f32x2 packed helpers --------------------------------------------------
__device__ __forceinline__ unsigned long long pack2(float a, float b) {
    unsigned long long r;
    asm("mov.b64 %0, {%1, %2};" : "=l"(r) : "r"(__float_as_uint(a)), "r"(__float_as_uint(b)));
    return r;
}
__device__ __forceinline__ unsigned long long fma2(unsigned long long a,
                                                   unsigned long long b,
                                                   unsigned long long c) {
    unsigned long long d;
    asm("fma.rn.f32x2 %0, %1, %2, %3;" : "=l"(d) : "l"(a), "l"(b), "l"(c));
    return d;
}
__device__ __forceinline__ float2 unpack2(unsigned long long v) {
    unsigned lo, hi;
    asm("mov.b64 {%0, %1}, %2;" : "=r"(lo), "=r"(hi) : "l"(v));
    return make_float2(__uint_as_float(lo), __uint_as_float(hi));
}

// ---------------------------------------------------------------------------
// K1: avgpool4 of inp (8,2,256,256,64) -> g_p0 (n,t,2,64,64). One output
// pixel per thread, 16 independent LDG.128; 4096 blocks (8/SM, 64 warps).
// R11 winner (-3.4us).
// ---------------------------------------------------------------------------
__global__ __launch_bounds__(256) void k_pool(const float* __restrict__ inp) {
    int bx = blockIdx.x;                     // 256 = Y(64) x Xq(4)
    int Y = bx >> 2, Xq = bx & 3;
    int c = blockIdx.y, n = blockIdx.z;
    __shared__ float sm[16 * 65];
    int tid = threadIdx.x;
    int t4 = tid & 15, Xi = tid >> 4;        // Xi 0..15
    int X = Xq * 16 + Xi;
    const float4* base =
        reinterpret_cast<const float4*>(inp + (((long long)(n * 2 + c) * 256 + 4 * Y) * 256) * 64) + t4;
    float4 acc = make_float4(0.f, 0.f, 0.f, 0.f);
#pragma unroll
    for (int dy = 0; dy < 4; ++dy)
#pragma unroll
        for (int dx = 0; dx < 4; ++dx) {
            float4 v = base[(dy * 256 + 4 * X + dx) * 16];
            acc.x += v.x; acc.y += v.y; acc.z += v.z; acc.w += v.w;
        }
    sm[Xi * 65 + 4 * t4 + 0] = acc.x * 0.0625f;
    sm[Xi * 65 + 4 * t4 + 1] = acc.y * 0.0625f;
    sm[Xi * 65 + 4 * t4 + 2] = acc.z * 0.0625f;
    sm[Xi * 65 + 4 * t4 + 3] = acc.w * 0.0625f;
    __syncthreads();
    float* ob = g_p0 + n * 524288 + c * 4096 + Y * 64 + Xq * 16;
#pragma unroll
    for (int k = 0; k < 4; ++k) {
        int idx = k * 256 + tid;
        int tw = idx >> 4, Xw = idx & 15;
        ob[tw * 8192 + Xw] = sm[Xw * 65 + tw];
    }
}

// ---------------------------------------------------------------------------
// K2: conv7 (2->4ch) on 64x64, 8-row tiles (R9 winner): thread = 2 y-rows
// x 4 couts x 2 t (f32x2). Grid (ytile8 8, tp 32, n 8) = 2048 blocks x 256.
// ---------------------------------------------------------------------------
__global__ __launch_bounds__(256) void k_conv1mm(const float* __restrict__ w0) {
    int tile = blockIdx.x, tp = blockIdx.y, n = blockIdx.z;
    int t0 = tp * 2;
    int tid = threadIdx.x;
    int x = tid & 63, q = tid >> 6;          // q: row-pair (rows 2q, 2q+1 of 8)

    __shared__ float2 si[1960];              // [cin 2][row 14][col 70], (t0,t1)
    __shared__ ulonglong2 swq[98][2];        // per tap: {(w0,w0),(w1,w1)},{(w2,w2),(w3,w3)}

    if (tid < 98) {
        int cin = tid / 49, j = tid - cin * 49;
        float wa = w0[(0 * 2 + cin) * 49 + j];
        float wb = w0[(1 * 2 + cin) * 49 + j];
        float wc = w0[(2 * 2 + cin) * 49 + j];
        float wd = w0[(3 * 2 + cin) * 49 + j];
        swq[tid][0] = make_ulonglong2(pack2(wa, wa), pack2(wb, wb));
        swq[tid][1] = make_ulonglong2(pack2(wc, wc), pack2(wd, wd));
    }

    int Y0 = tile * 8;
    const float* pt0 = g_p0 + n * 524288 + t0 * 8192;
    const float* pt1 = pt0 + 8192;
    for (int e = tid; e < 1960; e += 256) {
        int cin = e / 980, rem = e - cin * 980;
        int r = rem / 70, col = rem - r * 70;
        int gy = Y0 - 3 + r, gx = col - 3;
        float2 v = make_float2(0.f, 0.f);
        if ((unsigned)gy < 64u && (unsigned)gx < 64u) {
            int off = cin * 4096 + gy * 64 + gx;
            v.x = pt0[off];
            v.y = pt1[off];
        }
        si[e] = v;
    }
    __syncthreads();

    unsigned long long a[2][4];              // [row r][cout]
#pragma unroll
    for (int r = 0; r < 2; ++r)
#pragma unroll
        for (int co = 0; co < 4; ++co) a[r][co] = 0ull;

    const unsigned long long* sb = reinterpret_cast<const unsigned long long*>(si);
#pragma unroll 1
    for (int dx = 0; dx < 7; ++dx) {
#pragma unroll
        for (int cin = 0; cin < 2; ++cin) {
            const unsigned long long* colp = sb + cin * 980 + (q * 2) * 70 + (x + dx);
            unsigned long long v[8];
#pragma unroll
            for (int r = 0; r < 8; ++r) v[r] = colp[r * 70];
#pragma unroll
            for (int dy = 0; dy < 7; ++dy) {
                ulonglong2 wA = swq[cin * 49 + dy * 7 + dx][0];
                ulonglong2 wB = swq[cin * 49 + dy * 7 + dx][1];
                a[0][0] = fma2(v[dy],     wA.x, a[0][0]);
                a[0][1] = fma2(v[dy],     wA.y, a[0][1]);
                a[0][2] = fma2(v[dy],     wB.x, a[0][2]);
                a[0][3] = fma2(v[dy],     wB.y, a[0][3]);
                a[1][0] = fma2(v[dy + 1], wA.x, a[1][0]);
                a[1][1] = fma2(v[dy + 1], wA.y, a[1][1]);
                a[1][2] = fma2(v[dy + 1], wB.x, a[1][2]);
                a[1][3] = fma2(v[dy + 1], wB.y, a[1][3]);
            }
        }
    }

    long long base = ((long long)(n * 64 + t0) * 4) * 4096;
    int ybase = Y0 + q * 2;
#pragma unroll
    for (int r = 0; r < 2; ++r)
#pragma unroll
        for (int co = 0; co < 4; ++co) {
            float2 f = unpack2(a[r][co]);
            g_h1[base + co * 4096 + (ybase + r) * 64 + x]         = f.x;
            g_h1[base + 16384 + co * 4096 + (ybase + r) * 64 + x] = f.y;
        }
}

// ---------------------------------------------------------------------------
// K3: IAF scan layer 1 + fused avgpool4 -> g_p1. 2-deep prefetch.
// ---------------------------------------------------------------------------
__global__ __launch_bounds__(256) void k_iaf1() {
    int Yp = blockIdx.x, co = blockIdx.y, n = blockIdx.z;
    int tid = threadIdx.x;
    int w = tid >> 5, lane = tid & 31;
    int yin = lane >> 3, x8 = lane & 7;
    int x = w * 8 + x8;
    int y = Yp * 4 + yin;

    const float* hb = g_h1 + (long long)(n * 64) * 16384 + co * 4096 + y * 64 + x;
    float* ob = g_p1 + (n * 64) * 1024 + co * 256 + Yp * 16 + (x >> 2);
    const unsigned m = 0xffffffffu;

    float v = 0.f;
    float n0 = hb[0];
    float n1 = hb[16384];
    for (int t = 0; t < 64; ++t) {
        float hv = n0;
        n0 = n1;
        if (t < 62) n1 = hb[(t + 2) * 16384];
        v += hv;
        float sp = (v >= 1.f) ? 1.f : 0.f;
        v -= sp;
        sp += __shfl_down_sync(m, sp, 1);
        sp += __shfl_down_sync(m, sp, 2);
        sp += __shfl_down_sync(m, sp, 8);
        sp += __shfl_down_sync(m, sp, 16);
        if (yin == 0 && (x8 & 3) == 0) ob[t * 1024] = sp * 0.0625f;
    }
}

// ---------------------------------------------------------------------------
// K4: conv7 (4->8ch) on 16x16 — R10 measured-best shape (4 y-rows x 8 couts
// as 4 cout-pairs, 64-thread group per t, 2 t per 128-thread block) with the
// pack2 wart removed: smem tile stored pre-duplicated as float2(v,v) so the
// inner loop is pure LDS.64 + FMA2. Grid (tp 32, n 8) = 256 blocks.
// ---------------------------------------------------------------------------
__global__ __launch_bounds__(128) void k_conv2mm(const float* __restrict__ w1) {
    int tp = blockIdx.x, n = blockIdx.y;
    int tid = threadIdx.x;
    int sub = tid >> 6;                     // which t of the pair
    int lt = tid & 63;
    int x = lt & 15, q = lt >> 4;           // q: y-quad (rows q*4..q*4+3)
    int t = tp * 2 + sub;

    __shared__ float2 si[2][1936];          // [sub][cin 4][22][22], value DUPLICATED (v,v)
    __shared__ ulonglong2 swq[196][2];      // per tap: {(w0,w1),(w2,w3)},{(w4,w5),(w6,w7)}

    for (int e = tid; e < 196; e += 128) {
        int cin = e / 49, j = e - cin * 49;
        float w[8];
#pragma unroll
        for (int co = 0; co < 8; ++co) w[co] = w1[(co * 4 + cin) * 49 + j];
        swq[e][0] = make_ulonglong2(pack2(w[0], w[1]), pack2(w[2], w[3]));
        swq[e][1] = make_ulonglong2(pack2(w[4], w[5]), pack2(w[6], w[7]));
    }

    const float* pt = g_p1 + n * 65536 + t * 1024;
    for (int e = lt; e < 1936; e += 64) {
        int cin = e / 484, rem = e - cin * 484;
        int r = rem / 22, col = rem - r * 22;
        int gy = r - 3, gx = col - 3;
        float val = 0.f;
        if ((unsigned)gy < 16u && (unsigned)gx < 16u)
            val = pt[cin * 256 + gy * 16 + gx];
        si[sub][e] = make_float2(val, val);
    }
    __syncthreads();

    unsigned long long a[4][4];             // [row r][cout-pair p]
#pragma unroll
    for (int r = 0; r < 4; ++r)
#pragma unroll
        for (int p = 0; p < 4; ++p) a[r][p] = 0ull;

    const unsigned long long* sb = reinterpret_cast<const unsigned long long*>(si[sub]);
#pragma unroll 1
    for (int dx = 0; dx < 7; ++dx) {
#pragma unroll
        for (int cin = 0; cin < 4; ++cin) {
            const unsigned long long* colp = sb + cin * 484 + (q * 4) * 22 + (x + dx);
            unsigned long long vp[10];
#pragma unroll
            for (int r = 0; r < 10; ++r) vp[r] = colp[r * 22];
#pragma unroll
            for (int dy = 0; dy < 7; ++dy) {
                ulonglong2 wA = swq[cin * 49 + dy * 7 + dx][0];
                ulonglong2 wB = swq[cin * 49 + dy * 7 + dx][1];
#pragma unroll
                for (int r = 0; r < 4; ++r) {
                    a[r][0] = fma2(vp[dy + r], wA.x, a[r][0]);
                    a[r][1] = fma2(vp[dy + r], wA.y, a[r][1]);
                    a[r][2] = fma2(vp[dy + r], wB.x, a[r][2]);
                    a[r][3] = fma2(vp[dy + r], wB.y, a[r][3]);
                }
            }
        }
    }

    float* hb = g_h2 + (long long)(n * 64 + t) * 2048;
#pragma unroll
    for (int r = 0; r < 4; ++r) {
        int yo = (q * 4 + r) * 16 + x;
#pragma unroll
        for (int p = 0; p < 4; ++p) {
            float2 f = unpack2(a[r][p]);
            hb[(2 * p) * 256 + yo]     = f.x;
            hb[(2 * p + 1) * 256 + yo] = f.y;
        }
    }
}

// ---------------------------------------------------------------------------
// K5: IAF scan layer 2 + avgpool4 -> g_p2 (n,t,128). 2-deep prefetch.
// ---------------------------------------------------------------------------
__global__ __launch_bounds__(256) void k_iaf2() {
    int co = blockIdx.x, n = blockIdx.y;
    int tid = threadIdx.x;
    int w = tid >> 5, lane = tid & 31;
    int yin = lane >> 3, x8 = lane & 7;
    int y = (w >> 1) * 4 + yin;
    int x = (w & 1) * 8 + x8;
    int g = (y >> 2) * 4 + (x >> 2);

    const float* hb = g_h2 + (long long)(n * 64) * 2048 + co * 256 + y * 16 + x;
    float* ob = g_p2 + (n * 64) * 128 + co * 16 + g;
    const unsigned m = 0xffffffffu;

    float v = 0.f;
    float n0 = hb[0];
    float n1 = hb[2048];
    for (int t = 0; t < 64; ++t) {
        float hv = n0;
        n0 = n1;
        if (t < 62) n1 = hb[(t + 2) * 2048];
        v += hv;
        float sp = (v >= 1.f) ? 1.f : 0.f;
        v -= sp;
        sp += __shfl_down_sync(m, sp, 1);
        sp += __shfl_down_sync(m, sp, 2);
        sp += __shfl_down_sync(m, sp, 8);
        sp += __shfl_down_sync(m, sp, 16);
        if (yin == 0 && (x8 & 3) == 0) ob[t * 128] = sp * 0.0625f;
    }
}

// ---------------------------------------------------------------------------
// K6: out[n][cls][t] = sum_f feat[n][t][f] * wl[cls][f]   -> (8,2,64)
// ---------------------------------------------------------------------------
__global__ __launch_bounds__(128) void k_fc(const float* __restrict__ wl,
                                            float* __restrict__ out) {
    int b = blockIdx.x;          // n*64 + t
    int tid = threadIdx.x;
    float v = g_p2[b * 128 + tid];
    float c0 = v * wl[tid];
    float c1 = v * wl[128 + tid];
    const unsigned m = 0xffffffffu;
#pragma unroll
    for (int o = 16; o; o >>= 1) {
        c0 += __shfl_down_sync(m, c0, o);
        c1 += __shfl_down_sync(m, c1, o);
    }
    __shared__ float r0[4], r1[4];
    if ((tid & 31) == 0) { r0[tid >> 5] = c0; r1[tid >> 5] = c1; }
    __syncthreads();
    if (tid == 0) {
        int n = b >> 6, t = b & 63;
        out[n * 128 + t]      = (r0[0] + r0[1]) + (r0[2] + r0[3]);
        out[n * 128 + 64 + t] = (r1[0] + r1[1]) + (r1[2] + r1[3]);
    }
}

// ---------------------------------------------------------------------------
extern "C" void kernel_launch(void* const* d_in, const int* in_sizes, int n_in,
                              void* d_out, int out_size) {
    const float *inp = nullptr, *w0 = nullptr, *w1 = nullptr, *wl = nullptr;
    for (int i = 0; i < n_in; ++i) {
        switch (in_sizes[i]) {
            case 67108864: inp = (const float*)d_in[i]; break;  // (8,2,256,256,64)
            case 392:      w0  = (const float*)d_in[i]; break;  // (4,2,7,7)
            case 1568:     w1  = (const float*)d_in[i]; break;  // (8,4,7,7)
            case 256:      wl  = (const float*)d_in[i]; break;  // (2,128)
        }
    }
    if (!inp) inp = (const float*)d_in[0];
    if (!w0)  w0  = (const float*)d_in[1];
    if (!w1)  w1  = (const float*)d_in[2];
    if (!wl)  wl  = (const float*)d_in[3];

    k_pool   <<<dim3(256, 2, 8), 256>>>(inp);
    k_conv1mm<<<dim3(8, 32, 8),  256>>>(w0);
    k_iaf1   <<<dim3(16, 4, 8),  256>>>();
    k_conv2mm<<<dim3(32, 8),     128>>>(w1);
    k_iaf2   <<<dim3(8, 8),      256>>>();
    k_fc     <<<512,             128>>>(wl, (float*)d_out);
}

// round 15
// speedup vs baseline: 1.0099x; 1.0051x over previous
#include <cuda_runtime.h>

// ---------------------------------------------------------------------------
// Scratch (device globals — no dynamic allocation allowed)
// ---------------------------------------------------------------------------
__device__ float g_p0[8 * 64 * 2 * 64 * 64];   // pooled input   (n,t,2,64,64)  16 MB
__device__ float g_h1[8 * 64 * 4 * 64 * 64];   // conv1 out      (n,t,4,64,64)  33.5 MB
__device__ float g_p1[8 * 64 * 4 * 16 * 16];   // pooled spikes1 (n,t,4,16,16)   2 MB
__device__ float g_h2[8 * 64 * 8 * 16 * 16];   // conv2 out      (n,t,8,16,16)   4 MB
__device__ float g_p2[8 * 64 * 128];           // features       (n,t,128)     256 KB

// ---- f32x2 packed helpers --------------------------------------------------
__device__ __forceinline__ unsigned long long pack2(float a, float b) {
    unsigned long long r;
    asm("mov.b64 %0, {%1, %2};" : "=l"(r) : "r"(__float_as_uint(a)), "r"(__float_as_uint(b)));
    return r;
}
__device__ __forceinline__ unsigned long long fma2(unsigned long long a,
                                                   unsigned long long b,
                                                   unsigned long long c) {
    unsigned long long d;
    asm("fma.rn.f32x2 %0, %1, %2, %3;" : "=l"(d) : "l"(a), "l"(b), "l"(c));
    return d;
}
__device__ __forceinline__ float2 unpack2(unsigned long long v) {
    unsigned lo, hi;
    asm("mov.b64 {%0, %1}, %2;" : "=r"(lo), "=r"(hi) : "l"(v));
    return make_float2(__uint_as_float(lo), __uint_as_float(hi));
}

// ---------------------------------------------------------------------------
// K1: avgpool4 of inp (8,2,256,256,64) -> g_p0 (n,t,2,64,64). One output
// pixel per thread, 16 independent LDG.128; 4096 blocks (8/SM, 64 warps).
// ---------------------------------------------------------------------------
__global__ __launch_bounds__(256) void k_pool(const float* __restrict__ inp) {
    int bx = blockIdx.x;                     // 256 = Y(64) x Xq(4)
    int Y = bx >> 2, Xq = bx & 3;
    int c = blockIdx.y, n = blockIdx.z;
    __shared__ float sm[16 * 65];
    int tid = threadIdx.x;
    int t4 = tid & 15, Xi = tid >> 4;        // Xi 0..15
    int X = Xq * 16 + Xi;
    const float4* base =
        reinterpret_cast<const float4*>(inp + (((long long)(n * 2 + c) * 256 + 4 * Y) * 256) * 64) + t4;
    float4 acc = make_float4(0.f, 0.f, 0.f, 0.f);
#pragma unroll
    for (int dy = 0; dy < 4; ++dy)
#pragma unroll
        for (int dx = 0; dx < 4; ++dx) {
            float4 v = base[(dy * 256 + 4 * X + dx) * 16];
            acc.x += v.x; acc.y += v.y; acc.z += v.z; acc.w += v.w;
        }
    sm[Xi * 65 + 4 * t4 + 0] = acc.x * 0.0625f;
    sm[Xi * 65 + 4 * t4 + 1] = acc.y * 0.0625f;
    sm[Xi * 65 + 4 * t4 + 2] = acc.z * 0.0625f;
    sm[Xi * 65 + 4 * t4 + 3] = acc.w * 0.0625f;
    __syncthreads();
    float* ob = g_p0 + n * 524288 + c * 4096 + Y * 64 + Xq * 16;
#pragma unroll
    for (int k = 0; k < 4; ++k) {
        int idx = k * 256 + tid;
        int tw = idx >> 4, Xw = idx & 15;
        ob[tw * 8192 + Xw] = sm[Xw * 65 + tw];
    }
}

// ---------------------------------------------------------------------------
// K2: conv7 (2->4ch) on 64x64, 8-row tiles (R9 winner): thread = 2 y-rows
// x 4 couts x 2 t (f32x2). Grid (ytile8 8, tp 32, n 8) = 2048 blocks x 256.
// ---------------------------------------------------------------------------
__global__ __launch_bounds__(256) void k_conv1mm(const float* __restrict__ w0) {
    int tile = blockIdx.x, tp = blockIdx.y, n = blockIdx.z;
    int t0 = tp * 2;
    int tid = threadIdx.x;
    int x = tid & 63, q = tid >> 6;          // q: row-pair (rows 2q, 2q+1 of 8)

    __shared__ float2 si[1960];              // [cin 2][row 14][col 70], (t0,t1)
    __shared__ ulonglong2 swq[98][2];        // per tap: {(w0,w0),(w1,w1)},{(w2,w2),(w3,w3)}

    if (tid < 98) {
        int cin = tid / 49, j = tid - cin * 49;
        float wa = w0[(0 * 2 + cin) * 49 + j];
        float wb = w0[(1 * 2 + cin) * 49 + j];
        float wc = w0[(2 * 2 + cin) * 49 + j];
        float wd = w0[(3 * 2 + cin) * 49 + j];
        swq[tid][0] = make_ulonglong2(pack2(wa, wa), pack2(wb, wb));
        swq[tid][1] = make_ulonglong2(pack2(wc, wc), pack2(wd, wd));
    }

    int Y0 = tile * 8;
    const float* pt0 = g_p0 + n * 524288 + t0 * 8192;
    const float* pt1 = pt0 + 8192;
    for (int e = tid; e < 1960; e += 256) {
        int cin = e / 980, rem = e - cin * 980;
        int r = rem / 70, col = rem - r * 70;
        int gy = Y0 - 3 + r, gx = col - 3;
        float2 v = make_float2(0.f, 0.f);
        if ((unsigned)gy < 64u && (unsigned)gx < 64u) {
            int off = cin * 4096 + gy * 64 + gx;
            v.x = pt0[off];
            v.y = pt1[off];
        }
        si[e] = v;
    }
    __syncthreads();

    unsigned long long a[2][4];              // [row r][cout]
#pragma unroll
    for (int r = 0; r < 2; ++r)
#pragma unroll
        for (int co = 0; co < 4; ++co) a[r][co] = 0ull;

    const unsigned long long* sb = reinterpret_cast<const unsigned long long*>(si);
#pragma unroll 1
    for (int dx = 0; dx < 7; ++dx) {
#pragma unroll
        for (int cin = 0; cin < 2; ++cin) {
            const unsigned long long* colp = sb + cin * 980 + (q * 2) * 70 + (x + dx);
            unsigned long long v[8];
#pragma unroll
            for (int r = 0; r < 8; ++r) v[r] = colp[r * 70];
#pragma unroll
            for (int dy = 0; dy < 7; ++dy) {
                ulonglong2 wA = swq[cin * 49 + dy * 7 + dx][0];
                ulonglong2 wB = swq[cin * 49 + dy * 7 + dx][1];
                a[0][0] = fma2(v[dy],     wA.x, a[0][0]);
                a[0][1] = fma2(v[dy],     wA.y, a[0][1]);
                a[0][2] = fma2(v[dy],     wB.x, a[0][2]);
                a[0][3] = fma2(v[dy],     wB.y, a[0][3]);
                a[1][0] = fma2(v[dy + 1], wA.x, a[1][0]);
                a[1][1] = fma2(v[dy + 1], wA.y, a[1][1]);
                a[1][2] = fma2(v[dy + 1], wB.x, a[1][2]);
                a[1][3] = fma2(v[dy + 1], wB.y, a[1][3]);
            }
        }
    }

    long long base = ((long long)(n * 64 + t0) * 4) * 4096;
    int ybase = Y0 + q * 2;
#pragma unroll
    for (int r = 0; r < 2; ++r)
#pragma unroll
        for (int co = 0; co < 4; ++co) {
            float2 f = unpack2(a[r][co]);
            g_h1[base + co * 4096 + (ybase + r) * 64 + x]         = f.x;
            g_h1[base + 16384 + co * 4096 + (ybase + r) * 64 + x] = f.y;
        }
}

// ---------------------------------------------------------------------------
// K3: IAF scan layer 1 + fused avgpool4 -> g_p1. 2-deep prefetch.
// ---------------------------------------------------------------------------
__global__ __launch_bounds__(256) void k_iaf1() {
    int Yp = blockIdx.x, co = blockIdx.y, n = blockIdx.z;
    int tid = threadIdx.x;
    int w = tid >> 5, lane = tid & 31;
    int yin = lane >> 3, x8 = lane & 7;
    int x = w * 8 + x8;
    int y = Yp * 4 + yin;

    const float* hb = g_h1 + (long long)(n * 64) * 16384 + co * 4096 + y * 64 + x;
    float* ob = g_p1 + (n * 64) * 1024 + co * 256 + Yp * 16 + (x >> 2);
    const unsigned m = 0xffffffffu;

    float v = 0.f;
    float n0 = hb[0];
    float n1 = hb[16384];
    for (int t = 0; t < 64; ++t) {
        float hv = n0;
        n0 = n1;
        if (t < 62) n1 = hb[(t + 2) * 16384];
        v += hv;
        float sp = (v >= 1.f) ? 1.f : 0.f;
        v -= sp;
        sp += __shfl_down_sync(m, sp, 1);
        sp += __shfl_down_sync(m, sp, 2);
        sp += __shfl_down_sync(m, sp, 8);
        sp += __shfl_down_sync(m, sp, 16);
        if (yin == 0 && (x8 & 3) == 0) ob[t * 1024] = sp * 0.0625f;
    }
}

// ---------------------------------------------------------------------------
// K4: conv7 (4->8ch) on 16x16 — R10 shape REPACKAGED for one wave + 2
// warps/SMSP: 4 t-images per 256-thread block (four 64-thread groups),
// grid (tq 16, n 8) = 128 blocks x 8 warps. Each group: thread = 4 y-rows
// x 8 couts (4 cout-pair f32x2 accums). smem tile pre-duplicated (v,v) so
// the inner loop is pure LDS.64 + FMA2.
// ---------------------------------------------------------------------------
__global__ __launch_bounds__(256) void k_conv2mm(const float* __restrict__ w1) {
    int tq = blockIdx.x, n = blockIdx.y;
    int tid = threadIdx.x;
    int sub = tid >> 6;                     // which t of the quad (0..3)
    int lt = tid & 63;
    int x = lt & 15, q = lt >> 4;           // q: y-quad (rows q*4..q*4+3)
    int t = tq * 4 + sub;

    __shared__ float2 si[4][1936];          // [sub][cin 4][22][22], value DUPLICATED (v,v)
    __shared__ ulonglong2 swq[196][2];      // per tap: {(w0,w1),(w2,w3)},{(w4,w5),(w6,w7)}

    for (int e = tid; e < 196; e += 256) {
        int cin = e / 49, j = e - cin * 49;
        float w[8];
#pragma unroll
        for (int co = 0; co < 8; ++co) w[co] = w1[(co * 4 + cin) * 49 + j];
        swq[e][0] = make_ulonglong2(pack2(w[0], w[1]), pack2(w[2], w[3]));
        swq[e][1] = make_ulonglong2(pack2(w[4], w[5]), pack2(w[6], w[7]));
    }

    const float* pt = g_p1 + n * 65536 + t * 1024;
    for (int e = lt; e < 1936; e += 64) {
        int cin = e / 484, rem = e - cin * 484;
        int r = rem / 22, col = rem - r * 22;
        int gy = r - 3, gx = col - 3;
        float val = 0.f;
        if ((unsigned)gy < 16u && (unsigned)gx < 16u)
            val = pt[cin * 256 + gy * 16 + gx];
        si[sub][e] = make_float2(val, val);
    }
    __syncthreads();

    unsigned long long a[4][4];             // [row r][cout-pair p]
#pragma unroll
    for (int r = 0; r < 4; ++r)
#pragma unroll
        for (int p = 0; p < 4; ++p) a[r][p] = 0ull;

    const unsigned long long* sb = reinterpret_cast<const unsigned long long*>(si[sub]);
#pragma unroll 1
    for (int dx = 0; dx < 7; ++dx) {
#pragma unroll
        for (int cin = 0; cin < 4; ++cin) {
            const unsigned long long* colp = sb + cin * 484 + (q * 4) * 22 + (x + dx);
            unsigned long long vp[10];
#pragma unroll
            for (int r = 0; r < 10; ++r) vp[r] = colp[r * 22];
#pragma unroll
            for (int dy = 0; dy < 7; ++dy) {
                ulonglong2 wA = swq[cin * 49 + dy * 7 + dx][0];
                ulonglong2 wB = swq[cin * 49 + dy * 7 + dx][1];
#pragma unroll
                for (int r = 0; r < 4; ++r) {
                    a[r][0] = fma2(vp[dy + r], wA.x, a[r][0]);
                    a[r][1] = fma2(vp[dy + r], wA.y, a[r][1]);
                    a[r][2] = fma2(vp[dy + r], wB.x, a[r][2]);
                    a[r][3] = fma2(vp[dy + r], wB.y, a[r][3]);
                }
            }
        }
    }

    float* hb = g_h2 + (long long)(n * 64 + t) * 2048;
#pragma unroll
    for (int r = 0; r < 4; ++r) {
        int yo = (q * 4 + r) * 16 + x;
#pragma unroll
        for (int p = 0; p < 4; ++p) {
            float2 f = unpack2(a[r][p]);
            hb[(2 * p) * 256 + yo]     = f.x;
            hb[(2 * p + 1) * 256 + yo] = f.y;
        }
    }
}

// ---------------------------------------------------------------------------
// K5: IAF scan layer 2 + avgpool4 -> g_p2 (n,t,128). 2-deep prefetch.
// ---------------------------------------------------------------------------
__global__ __launch_bounds__(256) void k_iaf2() {
    int co = blockIdx.x, n = blockIdx.y;
    int tid = threadIdx.x;
    int w = tid >> 5, lane = tid & 31;
    int yin = lane >> 3, x8 = lane & 7;
    int y = (w >> 1) * 4 + yin;
    int x = (w & 1) * 8 + x8;
    int g = (y >> 2) * 4 + (x >> 2);

    const float* hb = g_h2 + (long long)(n * 64) * 2048 + co * 256 + y * 16 + x;
    float* ob = g_p2 + (n * 64) * 128 + co * 16 + g;
    const unsigned m = 0xffffffffu;

    float v = 0.f;
    float n0 = hb[0];
    float n1 = hb[2048];
    for (int t = 0; t < 64; ++t) {
        float hv = n0;
        n0 = n1;
        if (t < 62) n1 = hb[(t + 2) * 2048];
        v += hv;
        float sp = (v >= 1.f) ? 1.f : 0.f;
        v -= sp;
        sp += __shfl_down_sync(m, sp, 1);
        sp += __shfl_down_sync(m, sp, 2);
        sp += __shfl_down_sync(m, sp, 8);
        sp += __shfl_down_sync(m, sp, 16);
        if (yin == 0 && (x8 & 3) == 0) ob[t * 128] = sp * 0.0625f;
    }
}

// ---------------------------------------------------------------------------
// K6: out[n][cls][t] = sum_f feat[n][t][f] * wl[cls][f]   -> (8,2,64)
// ---------------------------------------------------------------------------
__global__ __launch_bounds__(128) void k_fc(const float* __restrict__ wl,
                                            float* __restrict__ out) {
    int b = blockIdx.x;          // n*64 + t
    int tid = threadIdx.x;
    float v = g_p2[b * 128 + tid];
    float c0 = v * wl[tid];
    float c1 = v * wl[128 + tid];
    const unsigned m = 0xffffffffu;
#pragma unroll
    for (int o = 16; o; o >>= 1) {
        c0 += __shfl_down_sync(m, c0, o);
        c1 += __shfl_down_sync(m, c1, o);
    }
    __shared__ float r0[4], r1[4];
    if ((tid & 31) == 0) { r0[tid >> 5] = c0; r1[tid >> 5] = c1; }
    __syncthreads();
    if (tid == 0) {
        int n = b >> 6, t = b & 63;
        out[n * 128 + t]      = (r0[0] + r0[1]) + (r0[2] + r0[3]);
        out[n * 128 + 64 + t] = (r1[0] + r1[1]) + (r1[2] + r1[3]);
    }
}

// ---------------------------------------------------------------------------
extern "C" void kernel_launch(void* const* d_in, const int* in_sizes, int n_in,
                              void* d_out, int out_size) {
    const float *inp = nullptr, *w0 = nullptr, *w1 = nullptr, *wl = nullptr;
    for (int i = 0; i < n_in; ++i) {
        switch (in_sizes[i]) {
            case 67108864: inp = (const float*)d_in[i]; break;  // (8,2,256,256,64)
            case 392:      w0  = (const float*)d_in[i]; break;  // (4,2,7,7)
            case 1568:     w1  = (const float*)d_in[i]; break;  // (8,4,7,7)
            case 256:      wl  = (const float*)d_in[i]; break;  // (2,128)
        }
    }
    if (!inp) inp = (const float*)d_in[0];
    if (!w0)  w0  = (const float*)d_in[1];
    if (!w1)  w1  = (const float*)d_in[2];
    if (!wl)  wl  = (const float*)d_in[3];

    k_pool   <<<dim3(256, 2, 8), 256>>>(inp);
    k_conv1mm<<<dim3(8, 32, 8),  256>>>(w0);
    k_iaf1   <<<dim3(16, 4, 8),  256>>>();
    k_conv2mm<<<dim3(16, 8),     256>>>(w1);
    k_iaf2   <<<dim3(8, 8),      256>>>();
    k_fc     <<<512,             128>>>(wl, (float*)d_out);
}

// round 17
// speedup vs baseline: 1.0234x; 1.0133x over previous
#include <cuda_runtime.h>

// ---------------------------------------------------------------------------
// Scratch (device globals — no dynamic allocation allowed)
// ---------------------------------------------------------------------------
__device__ float g_p0[8 * 64 * 2 * 64 * 64];   // pooled input   (n,t,2,64,64)  16 MB
__device__ float g_h1[8 * 64 * 4 * 64 * 64];   // conv1 out      (n,t,4,64,64)  33.5 MB
__device__ float g_p1[8 * 64 * 4 * 16 * 16];   // pooled spikes1 (n,t,4,16,16)   2 MB
__device__ float g_h2[8 * 64 * 8 * 16 * 16];   // conv2 out      (n,t,8,16,16)   4 MB
__device__ float g_p2[8 * 64 * 128];           // features       (n,t,128)     256 KB

// ---- f32x2 packed helpers --------------------------------------------------
__device__ __forceinline__ unsigned long long pack2(float a, float b) {
    unsigned long long r;
    asm("mov.b64 %0, {%1, %2};" : "=l"(r) : "r"(__float_as_uint(a)), "r"(__float_as_uint(b)));
    return r;
}
__device__ __forceinline__ unsigned long long fma2(unsigned long long a,
                                                   unsigned long long b,
                                                   unsigned long long c) {
    unsigned long long d;
    asm("fma.rn.f32x2 %0, %1, %2, %3;" : "=l"(d) : "l"(a), "l"(b), "l"(c));
    return d;
}
__device__ __forceinline__ float2 unpack2(unsigned long long v) {
    unsigned lo, hi;
    asm("mov.b64 {%0, %1}, %2;" : "=r"(lo), "=r"(hi) : "l"(v));
    return make_float2(__uint_as_float(lo), __uint_as_float(hi));
}

// ---------------------------------------------------------------------------
// K1: avgpool4 of inp (8,2,256,256,64) -> g_p0 (n,t,2,64,64). One output
// pixel per thread, 16 independent LDG.128; 4096 blocks.
// ---------------------------------------------------------------------------
__global__ __launch_bounds__(256) void k_pool(const float* __restrict__ inp) {
    int bx = blockIdx.x;                     // 256 = Y(64) x Xq(4)
    int Y = bx >> 2, Xq = bx & 3;
    int c = blockIdx.y, n = blockIdx.z;
    __shared__ float sm[16 * 65];
    int tid = threadIdx.x;
    int t4 = tid & 15, Xi = tid >> 4;        // Xi 0..15
    int X = Xq * 16 + Xi;
    const float4* base =
        reinterpret_cast<const float4*>(inp + (((long long)(n * 2 + c) * 256 + 4 * Y) * 256) * 64) + t4;
    float4 acc = make_float4(0.f, 0.f, 0.f, 0.f);
#pragma unroll
    for (int dy = 0; dy < 4; ++dy)
#pragma unroll
        for (int dx = 0; dx < 4; ++dx) {
            float4 v = base[(dy * 256 + 4 * X + dx) * 16];
            acc.x += v.x; acc.y += v.y; acc.z += v.z; acc.w += v.w;
        }
    sm[Xi * 65 + 4 * t4 + 0] = acc.x * 0.0625f;
    sm[Xi * 65 + 4 * t4 + 1] = acc.y * 0.0625f;
    sm[Xi * 65 + 4 * t4 + 2] = acc.z * 0.0625f;
    sm[Xi * 65 + 4 * t4 + 3] = acc.w * 0.0625f;
    __syncthreads();
    float* ob = g_p0 + n * 524288 + c * 4096 + Y * 64 + Xq * 16;
#pragma unroll
    for (int k = 0; k < 4; ++k) {
        int idx = k * 256 + tid;
        int tw = idx >> 4, Xw = idx & 15;
        ob[tw * 8192 + Xw] = sm[Xw * 65 + tw];
    }
}

// ---------------------------------------------------------------------------
// K2: conv7 (2->4ch) on 64x64, 8-row tiles. PDL: weights load before the
// grid-dependency wait; g_p0 reads after.
// ---------------------------------------------------------------------------
__global__ __launch_bounds__(256) void k_conv1mm(const float* __restrict__ w0) {
    int tile = blockIdx.x, tp = blockIdx.y, n = blockIdx.z;
    int t0 = tp * 2;
    int tid = threadIdx.x;
    int x = tid & 63, q = tid >> 6;          // q: row-pair (rows 2q, 2q+1 of 8)

    __shared__ float2 si[1960];              // [cin 2][row 14][col 70], (t0,t1)
    __shared__ ulonglong2 swq[98][2];

    if (tid < 98) {
        int cin = tid / 49, j = tid - cin * 49;
        float wa = w0[(0 * 2 + cin) * 49 + j];
        float wb = w0[(1 * 2 + cin) * 49 + j];
        float wc = w0[(2 * 2 + cin) * 49 + j];
        float wd = w0[(3 * 2 + cin) * 49 + j];
        swq[tid][0] = make_ulonglong2(pack2(wa, wa), pack2(wb, wb));
        swq[tid][1] = make_ulonglong2(pack2(wc, wc), pack2(wd, wd));
    }

    cudaGridDependencySynchronize();         // wait for k_pool's g_p0

    int Y0 = tile * 8;
    const float* pt0 = g_p0 + n * 524288 + t0 * 8192;
    const float* pt1 = pt0 + 8192;
    for (int e = tid; e < 1960; e += 256) {
        int cin = e / 980, rem = e - cin * 980;
        int r = rem / 70, col = rem - r * 70;
        int gy = Y0 - 3 + r, gx = col - 3;
        float2 v = make_float2(0.f, 0.f);
        if ((unsigned)gy < 64u && (unsigned)gx < 64u) {
            int off = cin * 4096 + gy * 64 + gx;
            v.x = pt0[off];
            v.y = pt1[off];
        }
        si[e] = v;
    }
    __syncthreads();

    unsigned long long a[2][4];              // [row r][cout]
#pragma unroll
    for (int r = 0; r < 2; ++r)
#pragma unroll
        for (int co = 0; co < 4; ++co) a[r][co] = 0ull;

    const unsigned long long* sb = reinterpret_cast<const unsigned long long*>(si);
#pragma unroll 1
    for (int dx = 0; dx < 7; ++dx) {
#pragma unroll
        for (int cin = 0; cin < 2; ++cin) {
            const unsigned long long* colp = sb + cin * 980 + (q * 2) * 70 + (x + dx);
            unsigned long long v[8];
#pragma unroll
            for (int r = 0; r < 8; ++r) v[r] = colp[r * 70];
#pragma unroll
            for (int dy = 0; dy < 7; ++dy) {
                ulonglong2 wA = swq[cin * 49 + dy * 7 + dx][0];
                ulonglong2 wB = swq[cin * 49 + dy * 7 + dx][1];
                a[0][0] = fma2(v[dy],     wA.x, a[0][0]);
                a[0][1] = fma2(v[dy],     wA.y, a[0][1]);
                a[0][2] = fma2(v[dy],     wB.x, a[0][2]);
                a[0][3] = fma2(v[dy],     wB.y, a[0][3]);
                a[1][0] = fma2(v[dy + 1], wA.x, a[1][0]);
                a[1][1] = fma2(v[dy + 1], wA.y, a[1][1]);
                a[1][2] = fma2(v[dy + 1], wB.x, a[1][2]);
                a[1][3] = fma2(v[dy + 1], wB.y, a[1][3]);
            }
        }
    }

    long long base = ((long long)(n * 64 + t0) * 4) * 4096;
    int ybase = Y0 + q * 2;
#pragma unroll
    for (int r = 0; r < 2; ++r)
#pragma unroll
        for (int co = 0; co < 4; ++co) {
            float2 f = unpack2(a[r][co]);
            g_h1[base + co * 4096 + (ybase + r) * 64 + x]         = f.x;
            g_h1[base + 16384 + co * 4096 + (ybase + r) * 64 + x] = f.y;
        }
}

// ---------------------------------------------------------------------------
// K3: IAF scan layer 1 + fused avgpool4 -> g_p1. PDL-gated g_h1 reads.
// ---------------------------------------------------------------------------
__global__ __launch_bounds__(256) void k_iaf1() {
    int Yp = blockIdx.x, co = blockIdx.y, n = blockIdx.z;
    int tid = threadIdx.x;
    int w = tid >> 5, lane = tid & 31;
    int yin = lane >> 3, x8 = lane & 7;
    int x = w * 8 + x8;
    int y = Yp * 4 + yin;

    const float* hb = g_h1 + (long long)(n * 64) * 16384 + co * 4096 + y * 64 + x;
    float* ob = g_p1 + (n * 64) * 1024 + co * 256 + Yp * 16 + (x >> 2);
    const unsigned m = 0xffffffffu;

    cudaGridDependencySynchronize();         // wait for k_conv1mm's g_h1

    float v = 0.f;
    float n0 = hb[0];
    float n1 = hb[16384];
    for (int t = 0; t < 64; ++t) {
        float hv = n0;
        n0 = n1;
        if (t < 62) n1 = hb[(t + 2) * 16384];
        v += hv;
        float sp = (v >= 1.f) ? 1.f : 0.f;
        v -= sp;
        sp += __shfl_down_sync(m, sp, 1);
        sp += __shfl_down_sync(m, sp, 2);
        sp += __shfl_down_sync(m, sp, 8);
        sp += __shfl_down_sync(m, sp, 16);
        if (yin == 0 && (x8 & 3) == 0) ob[t * 1024] = sp * 0.0625f;
    }
}

// ---------------------------------------------------------------------------
// K4: conv7 (4->8ch) on 16x16 — 4 t-images per 256-thread block, grid
// (tq 16, n 8) = 128 blocks. PDL: weights before wait, g_p1 after.
// ---------------------------------------------------------------------------
__global__ __launch_bounds__(256) void k_conv2mm(const float* __restrict__ w1) {
    int tq = blockIdx.x, n = blockIdx.y;
    int tid = threadIdx.x;
    int sub = tid >> 6;                     // which t of the quad (0..3)
    int lt = tid & 63;
    int x = lt & 15, q = lt >> 4;           // q: y-quad (rows q*4..q*4+3)
    int t = tq * 4 + sub;

    __shared__ float2 si[4][1936];          // [sub][cin 4][22][22], value DUPLICATED (v,v)
    __shared__ ulonglong2 swq[196][2];

    for (int e = tid; e < 196; e += 256) {
        int cin = e / 49, j = e - cin * 49;
        float w[8];
#pragma unroll
        for (int co = 0; co < 8; ++co) w[co] = w1[(co * 4 + cin) * 49 + j];
        swq[e][0] = make_ulonglong2(pack2(w[0], w[1]), pack2(w[2], w[3]));
        swq[e][1] = make_ulonglong2(pack2(w[4], w[5]), pack2(w[6], w[7]));
    }

    cudaGridDependencySynchronize();         // wait for k_iaf1's g_p1

    const float* pt = g_p1 + n * 65536 + t * 1024;
    for (int e = lt; e < 1936; e += 64) {
        int cin = e / 484, rem = e - cin * 484;
        int r = rem / 22, col = rem - r * 22;
        int gy = r - 3, gx = col - 3;
        float val = 0.f;
        if ((unsigned)gy < 16u && (unsigned)gx < 16u)
            val = pt[cin * 256 + gy * 16 + gx];
        si[sub][e] = make_float2(val, val);
    }
    __syncthreads();

    unsigned long long a[4][4];             // [row r][cout-pair p]
#pragma unroll
    for (int r = 0; r < 4; ++r)
#pragma unroll
        for (int p = 0; p < 4; ++p) a[r][p] = 0ull;

    const unsigned long long* sb = reinterpret_cast<const unsigned long long*>(si[sub]);
#pragma unroll 1
    for (int dx = 0; dx < 7; ++dx) {
#pragma unroll
        for (int cin = 0; cin < 4; ++cin) {
            const unsigned long long* colp = sb + cin * 484 + (q * 4) * 22 + (x + dx);
            unsigned long long vp[10];
#pragma unroll
            for (int r = 0; r < 10; ++r) vp[r] = colp[r * 22];
#pragma unroll
            for (int dy = 0; dy < 7; ++dy) {
                ulonglong2 wA = swq[cin * 49 + dy * 7 + dx][0];
                ulonglong2 wB = swq[cin * 49 + dy * 7 + dx][1];
#pragma unroll
                for (int r = 0; r < 4; ++r) {
                    a[r][0] = fma2(vp[dy + r], wA.x, a[r][0]);
                    a[r][1] = fma2(vp[dy + r], wA.y, a[r][1]);
                    a[r][2] = fma2(vp[dy + r], wB.x, a[r][2]);
                    a[r][3] = fma2(vp[dy + r], wB.y, a[r][3]);
                }
            }
        }
    }

    float* hb = g_h2 + (long long)(n * 64 + t) * 2048;
#pragma unroll
    for (int r = 0; r < 4; ++r) {
        int yo = (q * 4 + r) * 16 + x;
#pragma unroll
        for (int p = 0; p < 4; ++p) {
            float2 f = unpack2(a[r][p]);
            hb[(2 * p) * 256 + yo]     = f.x;
            hb[(2 * p + 1) * 256 + yo] = f.y;
        }
    }
}

// ---------------------------------------------------------------------------
// K5: IAF scan layer 2 + avgpool4 -> g_p2. PDL-gated g_h2 reads.
// ---------------------------------------------------------------------------
__global__ __launch_bounds__(256) void k_iaf2() {
    int co = blockIdx.x, n = blockIdx.y;
    int tid = threadIdx.x;
    int w = tid >> 5, lane = tid & 31;
    int yin = lane >> 3, x8 = lane & 7;
    int y = (w >> 1) * 4 + yin;
    int x = (w & 1) * 8 + x8;
    int g = (y >> 2) * 4 + (x >> 2);

    const float* hb = g_h2 + (long long)(n * 64) * 2048 + co * 256 + y * 16 + x;
    float* ob = g_p2 + (n * 64) * 128 + co * 16 + g;
    const unsigned m = 0xffffffffu;

    cudaGridDependencySynchronize();         // wait for k_conv2mm's g_h2

    float v = 0.f;
    float n0 = hb[0];
    float n1 = hb[2048];
    for (int t = 0; t < 64; ++t) {
        float hv = n0;
        n0 = n1;
        if (t < 62) n1 = hb[(t + 2) * 2048];
        v += hv;
        float sp = (v >= 1.f) ? 1.f : 0.f;
        v -= sp;
        sp += __shfl_down_sync(m, sp, 1);
        sp += __shfl_down_sync(m, sp, 2);
        sp += __shfl_down_sync(m, sp, 8);
        sp += __shfl_down_sync(m, sp, 16);
        if (yin == 0 && (x8 & 3) == 0) ob[t * 128] = sp * 0.0625f;
    }
}

// ---------------------------------------------------------------------------
// K6: out[n][cls][t] = sum_f feat[n][t][f] * wl[cls][f]. PDL: wl loads
// before the wait, g_p2 read after.
// ---------------------------------------------------------------------------
__global__ __launch_bounds__(128) void k_fc(const float* __restrict__ wl,
                                            float* __restrict__ out) {
    int b = blockIdx.x;          // n*64 + t
    int tid = threadIdx.x;
    float wv0 = wl[tid];
    float wv1 = wl[128 + tid];

    cudaGridDependencySynchronize();         // wait for k_iaf2's g_p2

    float v = g_p2[b * 128 + tid];
    float c0 = v * wv0;
    float c1 = v * wv1;
    const unsigned m = 0xffffffffu;
#pragma unroll
    for (int o = 16; o; o >>= 1) {
        c0 += __shfl_down_sync(m, c0, o);
        c1 += __shfl_down_sync(m, c1, o);
    }
    __shared__ float r0[4], r1[4];
    if ((tid & 31) == 0) { r0[tid >> 5] = c0; r1[tid >> 5] = c1; }
    __syncthreads();
    if (tid == 0) {
        int n = b >> 6, t = b & 63;
        out[n * 128 + t]      = (r0[0] + r0[1]) + (r0[2] + r0[3]);
        out[n * 128 + 64 + t] = (r1[0] + r1[1]) + (r1[2] + r1[3]);
    }
}

// ---------------------------------------------------------------------------
// PDL launch helper: programmatic stream serialization lets the next kernel's
// blocks launch (and run their independent prologue) while the predecessor
// drains; cudaGridDependencySynchronize() in-kernel enforces the data edge.
// ---------------------------------------------------------------------------
static void launch_pdl(const void* func, dim3 grid, dim3 block, void** args) {
    cudaLaunchConfig_t cfg = {};
    cfg.gridDim = grid;
    cfg.blockDim = block;
    cudaLaunchAttribute attr[1];
    attr[0].id = cudaLaunchAttributeProgrammaticStreamSerialization;
    attr[0].val.programmaticStreamSerializationAllowed = 1;
    cfg.attrs = attr;
    cfg.numAttrs = 1;
    cfg.stream = 0;
    cudaLaunchKernelExC(&cfg, func, args);
}

extern "C" void kernel_launch(void* const* d_in, const int* in_sizes, int n_in,
                              void* d_out, int out_size) {
    const float *inp = nullptr, *w0 = nullptr, *w1 = nullptr, *wl = nullptr;
    for (int i = 0; i < n_in; ++i) {
        switch (in_sizes[i]) {
            case 67108864: inp = (const float*)d_in[i]; break;  // (8,2,256,256,64)
            case 392:      w0  = (const float*)d_in[i]; break;  // (4,2,7,7)
            case 1568:     w1  = (const float*)d_in[i]; break;  // (8,4,7,7)
            case 256:      wl  = (const float*)d_in[i]; break;  // (2,128)
        }
    }
    if (!inp) inp = (const float*)d_in[0];
    if (!w0)  w0  = (const float*)d_in[1];
    if (!w1)  w1  = (const float*)d_in[2];
    if (!wl)  wl  = (const float*)d_in[3];
    float* out = (float*)d_out;

    k_pool<<<dim3(256, 2, 8), 256>>>(inp);

    { void* a[] = { (void*)&w0 };
      launch_pdl((const void*)k_conv1mm, dim3(8, 32, 8), dim3(256), a); }
    { void* a0[1]; (void)a0;
      launch_pdl((const void*)k_iaf1, dim3(16, 4, 8), dim3(256), nullptr); }
    { void* a[] = { (void*)&w1 };
      launch_pdl((const void*)k_conv2mm, dim3(16, 8), dim3(256), a); }
    launch_pdl((const void*)k_iaf2, dim3(8, 8), dim3(256), nullptr);
    { void* a[] = { (void*)&wl, (void*)&out };
      launch_pdl((const void*)k_fc, dim3(512), dim3(128), a); }
}